// round 7
// baseline (speedup 1.0000x reference)
#include <cuda_runtime.h>
#include <math.h>

#define NB   2048
#define NTHR 1024

// ---------------- global scratch -------------------------------------------
__device__ float2 g_psi[NB * 4 * 10];       // encoded per-wire vectors
__device__ float2 g_Elay[8 * 100];          // merged layer 10x10 complex gates (D@S)
__device__ __align__(16) float2 g_Xm[2][10000];   // scaled generators (CX, BS)
__device__ __align__(16) float2 g_Tp[2][2][10000];// Taylor term ping-pong [parity][m]
__device__ __align__(16) float2 g_Sp[2][2][10000];// partial sum ping-pong [parity][m]
__device__ __align__(16) float  g_CXp[12000];     // CX real, packed [k1][o][12] (fallback)
__device__ float2 g_BSb[670];                     // BS photon-number blocks packed
// eigen-CX machinery
__device__ float  g_V[100];                       // eigenvectors of X=a+ad (columns)
__device__ __align__(16) float g_f1[10000];       // (V^T (x) I) CX
__device__ __align__(16) float g_f2[10000];       // (V^T (x) I) CX (V (x) I)
__device__ __align__(16) float g_Rp[1200];        // conditioned blocks R_a [a][j][12]
__device__ __align__(16) float g_Vt[120];         // V^T padded rows
__device__ __align__(16) float g_Vm[120];         // V  padded rows
__device__ int g_flag;                            // 1 = eigen path validated

// BS block tables: sizes, packed offsets, lo = max(0, N-9)
__device__ const int d_bsz[19] = {1,2,3,4,5,6,7,8,9,10,9,8,7,6,5,4,3,2,1};
__device__ const int d_off[19] = {0,1,5,14,30,55,91,140,204,285,385,466,530,579,615,640,656,665,669};
__device__ const int d_lo[19]  = {0,0,0,0,0,0,0,0,0,0,1,2,3,4,5,6,7,8,9};

// ---------------- complex helpers ------------------------------------------
__device__ __forceinline__ float2 cmul(float2 a, float2 b) {
    return make_float2(a.x * b.x - a.y * b.y, a.x * b.y + a.y * b.x);
}
__device__ __forceinline__ void cmacc(float2& acc, float2 a, float2 b) {
    acc.x = fmaf(a.x, b.x, fmaf(-a.y, b.y, acc.x));
    acc.y = fmaf(a.x, b.y, fmaf( a.y, b.x, acc.y));
}

// ---------------- 10x10 expm (block-cooperative, >=128 thr) -----------------
__device__ void expm10(float2* X, float2* S, float2* T, float2* T2, float* red, int t) {
    if (t < 10) {
        float s = 0.f;
        for (int j = 0; j < 10; j++) { float2 v = X[t * 10 + j]; s += fabsf(v.x) + fabsf(v.y); }
        red[t] = s;
    }
    __syncthreads();
    if (t == 0) {
        float m = 0.f;
        for (int i = 0; i < 10; i++) m = fmaxf(m, red[i]);
        int s = 0;
        while (m > 0.5f && s < 40) { m *= 0.5f; s++; }
        red[10] = (float)s;
    }
    __syncthreads();
    int s = (int)red[10];
    float sc = ldexpf(1.f, -s);
    if (t < 100) {
        X[t].x *= sc; X[t].y *= sc;
        T[t] = X[t];
        float2 v = X[t];
        if (t % 11 == 0) v.x += 1.f;
        S[t] = v;
    }
    __syncthreads();
    for (int j = 2; j <= 13; j++) {
        float inv = 1.f / (float)j;
        if (t < 100) {
            int i = t / 10, c = t % 10;
            float2 acc = make_float2(0.f, 0.f);
#pragma unroll
            for (int k = 0; k < 10; k++) cmacc(acc, T[i * 10 + k], X[k * 10 + c]);
            T2[t] = make_float2(acc.x * inv, acc.y * inv);
        }
        __syncthreads();
        if (t < 100) { T[t] = T2[t]; S[t].x += T2[t].x; S[t].y += T2[t].y; }
        __syncthreads();
    }
    for (int it = 0; it < s; it++) {
        if (t < 100) {
            int i = t / 10, c = t % 10;
            float2 acc = make_float2(0.f, 0.f);
#pragma unroll
            for (int k = 0; k < 10; k++) cmacc(acc, S[i * 10 + k], S[k * 10 + c]);
            T2[t] = acc;
        }
        __syncthreads();
        if (t < 100) S[t] = T2[t];
        __syncthreads();
    }
}

// ---------------- prep: encoding vectors + layer 10x10 gates ----------------
__global__ void k_enc(const float* __restrict__ jets, const float* __restrict__ s_scale,
                      const float* __restrict__ dmag, const float* __restrict__ dph,
                      const float* __restrict__ smag, const float* __restrict__ sph) {
    __shared__ float2 B0[100], B1[100], B2[100], B3[100], B4[100];
    __shared__ float red[16];
    int t = threadIdx.x;
    int id = blockIdx.x;

    float r_s, p_s, r_d, p_d;
    if (id < NB * 4) {
        const float* j3 = jets + id * 3;
        float eta = j3[0], ph = j3[1], pt = j3[2];
        float sc = 10.f / (1.f + expf(-s_scale[0])) + 0.01f;
        r_s = eta;      p_s = pt * ph * 0.5f;
        r_d = sc * pt;  p_d = eta;
    } else {
        int lw = id - NB * 4;
        r_s = smag[lw]; p_s = sph[lw];
        r_d = dmag[lw]; p_d = dph[lw];
    }

    float2 z = make_float2(r_s * cosf(p_s), r_s * sinf(p_s));
    if (t < 100) {
        int i = t / 10, j = t % 10;
        float2 g = make_float2(0.f, 0.f);
        if (j == i + 2) {
            float v = sqrtf((float)((i + 1) * (i + 2)));
            g.x = 0.5f * z.x * v;  g.y = -0.5f * z.y * v;
        } else if (i == j + 2) {
            float v = sqrtf((float)((j + 1) * (j + 2)));
            g.x = -0.5f * z.x * v; g.y = -0.5f * z.y * v;
        }
        B0[t] = g;
    }
    __syncthreads();
    expm10(B0, B1, B2, B3, red, t);
    __syncthreads();

    float2 al = make_float2(r_d * cosf(p_d), r_d * sinf(p_d));
    if (t < 100) {
        int i = t / 10, j = t % 10;
        float2 g = make_float2(0.f, 0.f);
        if (i == j + 1) {
            float v = sqrtf((float)(j + 1));
            g.x = al.x * v;  g.y = al.y * v;
        } else if (j == i + 1) {
            float v = sqrtf((float)(i + 1));
            g.x = -al.x * v; g.y = al.y * v;
        }
        B0[t] = g;
    }
    __syncthreads();
    expm10(B0, B4, B2, B3, red, t);
    __syncthreads();

    if (id < NB * 4) {
        if (t < 10) {
            float2 acc = make_float2(0.f, 0.f);
#pragma unroll
            for (int k = 0; k < 10; k++) cmacc(acc, B4[t * 10 + k], B1[k * 10 + 0]);
            g_psi[id * 10 + t] = acc;
        }
    } else {
        if (t < 100) {
            int i = t / 10, j = t % 10;
            float2 acc = make_float2(0.f, 0.f);
#pragma unroll
            for (int k = 0; k < 10; k++) cmacc(acc, B4[i * 10 + k], B1[k * 10 + j]);
            g_Elay[(id - NB * 4) * 100 + t] = acc;
        }
    }
}

// ---------------- prep: Jacobi eigendecomposition of X = a + ad -------------
__global__ void k_eig() {
    if (threadIdx.x != 0 || blockIdx.x != 0) return;
    float A[10][10], V[10][10];
    for (int i = 0; i < 10; i++)
        for (int j = 0; j < 10; j++) { A[i][j] = 0.f; V[i][j] = (i == j) ? 1.f : 0.f; }
    for (int i = 0; i < 9; i++) { A[i][i + 1] = sqrtf((float)(i + 1)); A[i + 1][i] = A[i][i + 1]; }

    for (int sweep = 0; sweep < 30; sweep++) {
        for (int p = 0; p < 9; p++) {
            for (int q = p + 1; q < 10; q++) {
                float apq = A[p][q];
                if (fabsf(apq) < 1e-12f) continue;
                float app = A[p][p], aqq = A[q][q];
                float theta = (aqq - app) / (2.f * apq);
                float tt = (theta >= 0.f ? 1.f : -1.f) / (fabsf(theta) + sqrtf(theta * theta + 1.f));
                float c = rsqrtf(tt * tt + 1.f);
                float sj = tt * c;
                A[p][p] = app - tt * apq;
                A[q][q] = aqq + tt * apq;
                A[p][q] = 0.f; A[q][p] = 0.f;
                for (int i = 0; i < 10; i++) {
                    if (i == p || i == q) continue;
                    float aip = A[i][p], aiq = A[i][q];
                    A[i][p] = c * aip - sj * aiq; A[p][i] = A[i][p];
                    A[i][q] = sj * aip + c * aiq; A[q][i] = A[i][q];
                }
                for (int i = 0; i < 10; i++) {
                    float vip = V[i][p], viq = V[i][q];
                    V[i][p] = c * vip - sj * viq;
                    V[i][q] = sj * vip + c * viq;
                }
            }
        }
    }
    for (int i = 0; i < 10; i++)
        for (int k = 0; k < 10; k++) g_V[i * 10 + k] = V[i][k];
}

// ---------------- prep pipeline: 100x100 expm via parallel launches ---------
__global__ void k_g_init() {
    int m = blockIdx.x;            // 0 = CX, 1 = BS
    int t = threadIdx.x;
    const float PIO4 = 0.7853981633974483f;
    const float SCF = 1.0f / 64.0f;
    for (int e = t; e < 10000; e += blockDim.x) {
        int o = e / 100, in = e % 100;
        int i = o / 10, j = o % 10, k = in / 10, l = in % 10;
        float2 g = make_float2(0.f, 0.f);
        if (m == 0) {
            float x1 = 0.f;
            if (k == i + 1) x1 = sqrtf((float)(i + 1));
            else if (i == k + 1) x1 = sqrtf((float)(k + 1));
            float y1 = 0.f;
            if (l == j + 1) y1 += sqrtf((float)(j + 1));
            if (j == l + 1) y1 -= sqrtf((float)(l + 1));
            g.x = -0.5f * x1 * y1;
        } else {
            float v = 0.f;
            if (k == i + 1 && j == l + 1) v += sqrtf((float)(i + 1)) * sqrtf((float)(l + 1));
            if (i == k + 1 && l == j + 1) v += sqrtf((float)(k + 1)) * sqrtf((float)(j + 1));
            g.y = PIO4 * v;
        }
        g.x *= SCF; g.y *= SCF;
        g_Xm[m][e] = g;
        g_Tp[0][m][e] = g;
        float2 s = g;
        if (o == in) s.x += 1.f;
        g_Sp[0][m][e] = s;
    }
}

// T_new = T_old @ X / j ; S += T_new.  X staged in smem.
__global__ void k_g_taylor(int jterm, int par) {
    extern __shared__ float2 Xs[];                // 10000
    int m = blockIdx.x / 20, rblk = blockIdx.x % 20;
    for (int e = threadIdx.x; e < 10000; e += blockDim.x) Xs[e] = g_Xm[m][e];
    __syncthreads();
    int t = threadIdx.x;
    if (t >= 500) return;
    int row = rblk * 5 + t / 100, col = t % 100;
    const float2* T = g_Tp[par][m];
    float inv = 1.f / (float)jterm;
    float2 acc = make_float2(0.f, 0.f);
    for (int k = 0; k < 100; k++) cmacc(acc, T[row * 100 + k], Xs[k * 100 + col]);
    acc.x *= inv; acc.y *= inv;
    g_Tp[1 - par][m][row * 100 + col] = acc;
    float2 s = g_Sp[0][m][row * 100 + col];
    s.x += acc.x; s.y += acc.y;
    g_Sp[0][m][row * 100 + col] = s;
}

// S_new = S_old @ S_old, S staged in smem. parity 0,1,0,1,0,1 -> final g_Sp[0].
__global__ void k_g_square(int par) {
    extern __shared__ float2 Ss[];                // 10000
    int m = blockIdx.x / 20, rblk = blockIdx.x % 20;
    for (int e = threadIdx.x; e < 10000; e += blockDim.x) Ss[e] = g_Sp[par][m][e];
    __syncthreads();
    int t = threadIdx.x;
    if (t >= 500) return;
    int row = rblk * 5 + t / 100, col = t % 100;
    float2 acc = make_float2(0.f, 0.f);
    for (int k = 0; k < 100; k++) cmacc(acc, Ss[row * 100 + k], Ss[k * 100 + col]);
    g_Sp[1 - par][m][row * 100 + col] = acc;
}

// ---------------- prep: eigen conjugation of dense CX -----------------------
// Dt = (V^T (x) I) @ CX   (CX exactly real: take .x)
__global__ void k_conj1() {
    int t = blockIdx.x * blockDim.x + threadIdx.x;
    if (t >= 10000) return;
    int r1 = t / 100, in = t % 100;
    int aa = r1 / 10, j = r1 % 10;
    float acc = 0.f;
#pragma unroll
    for (int i = 0; i < 10; i++)
        acc += g_V[i * 10 + aa] * g_Sp[0][0][(i * 10 + j) * 100 + in].x;
    g_f1[t] = acc;
}
// D = Dt @ (V (x) I)
__global__ void k_conj2() {
    int t = blockIdx.x * blockDim.x + threadIdx.x;
    if (t >= 10000) return;
    int r1 = t / 100, in = t % 100;
    int bb = in / 10, l = in % 10;
    float acc = 0.f;
#pragma unroll
    for (int k = 0; k < 10; k++)
        acc += g_f1[r1 * 100 + k * 10 + l] * g_V[k * 10 + bb];
    g_f2[t] = acc;
}
// Validate block-diagonality; pack R_a, V^T, V. flag=0 -> k_main falls back.
__global__ void k_checkpack() {
    __shared__ int ok;
    int t = threadIdx.x;
    if (t == 0) ok = 1;
    __syncthreads();
    for (int e = t; e < 10000; e += blockDim.x) {
        int r1 = e / 100, in = e % 100;
        if ((r1 / 10) != (in / 10) && fabsf(g_f2[e]) > 2e-4f) atomicAnd(&ok, 0);
    }
    __syncthreads();
    if (t == 0) g_flag = ok;
    for (int e = t; e < 1200; e += blockDim.x) {
        int a = e / 120, rem = e % 120, j = rem / 12, l = rem % 12;
        g_Rp[e] = (l < 10) ? g_f2[(a * 10 + j) * 100 + a * 10 + l] : 0.f;
    }
    for (int e = t; e < 120; e += blockDim.x) {
        int r = e / 12, c = e % 12;
        g_Vt[e] = (c < 10) ? g_V[c * 10 + r] : 0.f;   // V^T row r
        g_Vm[e] = (c < 10) ? g_V[r * 10 + c] : 0.f;   // V   row r
    }
}

// ---------------- prep: pack fallback CX real [k1][o][12] + BS blocks -------
__global__ void k_pack() {
    int t = blockIdx.x * blockDim.x + threadIdx.x;
    if (t < 12000) {
        int kk = t / 1200, rem = t % 1200;
        int o = rem / 12, ll = rem % 12;
        g_CXp[t] = (ll < 10) ? g_Sp[0][0][o * 100 + kk * 10 + ll].x : 0.f;
    } else if (t < 13900) {
        int e = t - 12000;
        int N = e / 100, rc = e % 100;
        int r = rc / 10, cc = rc % 10;
        int b = d_bsz[N], lo = d_lo[N];
        if (r < b && cc < b) {
            int i = lo + r,  j = N - i;
            int k = lo + cc, l = N - k;
            g_BSb[d_off[N] + r * b + cc] = g_Sp[0][1][(i * 10 + j) * 100 + (k * 10 + l)];
        }
    }
}

// ---------------- main kernel passes ----------------------------------------
// Dense real two-mode CX gate (fallback; proven R6).
template<int S1, int S2, int SA, int SB>
__device__ __forceinline__ void pass_cx(float2* st, const float* Up, int tid) {
    float2 acc[10];
    int base = 0, rb = 0;
    if (tid < 1000) {
        rb = tid / 100;
        int sp = tid - rb * 100;
        base = (sp / 10) * SA + (sp % 10) * SB;
#pragma unroll
        for (int q = 0; q < 10; q++) acc[q] = make_float2(0.f, 0.f);
#pragma unroll 1
        for (int kk = 0; kk < 10; kk++) {
            float2 xr[10];
            const float2* rowp = st + base + kk * S1;
#pragma unroll
            for (int ll = 0; ll < 10; ll++) xr[ll] = rowp[ll * S2];
            const float* Uk = Up + kk * 1200 + rb * 120;
#pragma unroll
            for (int q = 0; q < 10; q++) {
                const float* Ur = Uk + q * 12;
                float4 u0 = *(const float4*)Ur;
                float4 u1 = *(const float4*)(Ur + 4);
                float2 u2 = *(const float2*)(Ur + 8);
                float ax = acc[q].x, ay = acc[q].y;
                ax = fmaf(u0.x, xr[0].x, ax); ay = fmaf(u0.x, xr[0].y, ay);
                ax = fmaf(u0.y, xr[1].x, ax); ay = fmaf(u0.y, xr[1].y, ay);
                ax = fmaf(u0.z, xr[2].x, ax); ay = fmaf(u0.z, xr[2].y, ay);
                ax = fmaf(u0.w, xr[3].x, ax); ay = fmaf(u0.w, xr[3].y, ay);
                ax = fmaf(u1.x, xr[4].x, ax); ay = fmaf(u1.x, xr[4].y, ay);
                ax = fmaf(u1.y, xr[5].x, ax); ay = fmaf(u1.y, xr[5].y, ay);
                ax = fmaf(u1.z, xr[6].x, ax); ay = fmaf(u1.z, xr[6].y, ay);
                ax = fmaf(u1.w, xr[7].x, ax); ay = fmaf(u1.w, xr[7].y, ay);
                ax = fmaf(u2.x, xr[8].x, ax); ay = fmaf(u2.x, xr[8].y, ay);
                ax = fmaf(u2.y, xr[9].x, ax); ay = fmaf(u2.y, xr[9].y, ay);
                acc[q].x = ax; acc[q].y = ay;
            }
        }
    }
    __syncthreads();
    if (tid < 1000) {
#pragma unroll
        for (int q = 0; q < 10; q++)
            st[base + rb * S1 + q * S2] = acc[q];
    }
    __syncthreads();
}

// Real single-mode pass, optionally conditioned on index a (stride SA).
// SW = target-mode stride; (SA,SB,SC) = spectator strides; M rows padded to 12.
template<int SW, int SA, int SB, int SC, bool COND>
__device__ __forceinline__ void pass_crx(float2* st, const float* Mtab, int tid) {
    if (tid < 1000) {
        int a = tid / 100; int r2 = tid - a * 100; int bq = r2 / 10; int cq = r2 - bq * 10;
        int base = a * SA + bq * SB + cq * SC;
        const float* M = COND ? (Mtab + a * 120) : Mtab;
        float2 in[10];
#pragma unroll
        for (int k = 0; k < 10; k++) in[k] = st[base + k * SW];
#pragma unroll
        for (int i = 0; i < 10; i++) {
            float4 m0 = *(const float4*)(M + i * 12);
            float4 m1 = *(const float4*)(M + i * 12 + 4);
            float2 m2 = *(const float2*)(M + i * 12 + 8);
            float ax = m0.x * in[0].x, ay = m0.x * in[0].y;
            ax = fmaf(m0.y, in[1].x, ax); ay = fmaf(m0.y, in[1].y, ay);
            ax = fmaf(m0.z, in[2].x, ax); ay = fmaf(m0.z, in[2].y, ay);
            ax = fmaf(m0.w, in[3].x, ax); ay = fmaf(m0.w, in[3].y, ay);
            ax = fmaf(m1.x, in[4].x, ax); ay = fmaf(m1.x, in[4].y, ay);
            ax = fmaf(m1.y, in[5].x, ax); ay = fmaf(m1.y, in[5].y, ay);
            ax = fmaf(m1.z, in[6].x, ax); ay = fmaf(m1.z, in[6].y, ay);
            ax = fmaf(m1.w, in[7].x, ax); ay = fmaf(m1.w, in[7].y, ay);
            ax = fmaf(m2.x, in[8].x, ax); ay = fmaf(m2.x, in[8].y, ay);
            ax = fmaf(m2.y, in[9].x, ax); ay = fmaf(m2.y, in[9].y, ay);
            st[base + i * SW] = make_float2(ax, ay);
        }
    }
    __syncthreads();
}

// BS photon-number-block pass. SI/SJ = strides of m1/m2; SA/SB spectators.
template<int SI, int SJ, int SA, int SB>
__device__ __forceinline__ void pass_bs(float2* st, const float2* BSb, int tid) {
    for (int it = tid; it < 1900; it += NTHR) {
        int N = it / 100; int sp = it - N * 100;
        int b = d_bsz[N], lo = d_lo[N], of = d_off[N];
        int spa = sp / 10;
        int base = spa * SA + (sp - spa * 10) * SB;
        int ilo = base + lo * SI + (N - lo) * SJ;
        const int step = SI - SJ;
        float2 in[10];
        for (int c = 0; c < b; c++) in[c] = st[ilo + c * step];
        const float2* Bb = BSb + of;
        for (int r = 0; r < b; r++) {
            float2 acc = make_float2(0.f, 0.f);
            const float2* Br = Bb + r * b;
            for (int c = 0; c < b; c++) cmacc(acc, Br[c], in[c]);
            st[ilo + r * step] = acc;
        }
    }
    __syncthreads();
}

// Complex single-mode gate, in-place per fiber.
__device__ __forceinline__ void pass_e(float2* st, const float2* E, int sm, int tid) {
    if (tid < 1000) {
        int base = (tid / sm) * (sm * 10) + (tid % sm);
        float2 in[10];
#pragma unroll
        for (int k = 0; k < 10; k++) in[k] = st[base + k * sm];
#pragma unroll
        for (int i = 0; i < 10; i++) {
            float2 a = make_float2(0.f, 0.f);
#pragma unroll
            for (int k = 0; k < 10; k++) cmacc(a, E[i * 10 + k], in[k]);
            st[base + i * sm] = a;
        }
    }
    __syncthreads();
}

// ---------------- main: whole circuit per batch element in SMEM -------------
// SMEM floats: st[20000] | Utab[12000] (CXp OR Rt/Vt/Vm) | BSb[1340] | Eg[1600]
#define SM_UT  20000
#define SM_BSB 32000
#define SM_EG  33340
#define SM_FLOATS 34940

__global__ void __launch_bounds__(NTHR, 1) k_main(const float* __restrict__ w_dense,
                                                  const float* __restrict__ b_dense,
                                                  float* __restrict__ out) {
    extern __shared__ float shf[];
    float2* st  = (float2*)shf;
    float*  Ut  = shf + SM_UT;
    float2* BSb = (float2*)(shf + SM_BSB);
    float2* Eg  = (float2*)(shf + SM_EG);
    __shared__ float2 psi[40];
    __shared__ float redsh[96];

    int tid = threadIdx.x;
    int b = blockIdx.x;
    const int useE = g_flag;

    // ---- stage tables ----
    if (useE) {
        for (int e = tid; e < 1200; e += NTHR) Ut[e] = g_Rp[e];
        for (int e = tid; e < 120; e += NTHR) { Ut[1200 + e] = g_Vt[e]; Ut[1320 + e] = g_Vm[e]; }
    } else {
        const float4* src = (const float4*)g_CXp;
        float4* dst = (float4*)Ut;
        for (int e = tid; e < 3000; e += NTHR) dst[e] = src[e];
    }
    for (int idx = tid; idx < 670; idx += NTHR) BSb[idx] = g_BSb[idx];
    for (int idx = tid; idx < 800; idx += NTHR) Eg[idx] = g_Elay[idx];
    if (tid < 40) psi[tid] = g_psi[b * 40 + tid];
    __syncthreads();

    // ---- init: outer product of encoded per-wire vectors ----
    for (int e = tid; e < 10000; e += NTHR) {
        int i0 = e / 1000; int r = e - i0 * 1000;
        int i1 = r / 100;  r -= i1 * 100;
        int i2 = r / 10;   int i3 = r - i2 * 10;
        st[e] = cmul(cmul(psi[i0], psi[10 + i1]), cmul(psi[20 + i2], psi[30 + i3]));
    }
    __syncthreads();

    const float* Rt = Ut;
    const float* Vt = Ut + 1200;
    const float* Vm = Ut + 1320;

#pragma unroll 1
    for (int L = 0; L < 2; L++) {
        if (useE) {
            // chain mode0: V^T(0), R(0->1), R(0->2), R(0->3), V(0)
            pass_crx<1000, 100, 10, 1, false>(st, Vt, tid);
            pass_crx<100, 1000, 10, 1, true >(st, Rt, tid);
            pass_crx<10, 1000, 100, 1, true >(st, Rt, tid);
            pass_crx<1, 1000, 100, 10, true >(st, Rt, tid);
            pass_crx<1000, 100, 10, 1, false>(st, Vm, tid);
            // chain mode1: V^T(1), R(1->2), R(1->3), V(1)
            pass_crx<100, 1000, 10, 1, false>(st, Vt, tid);
            pass_crx<10, 100, 1000, 1, true >(st, Rt, tid);
            pass_crx<1, 100, 1000, 10, true >(st, Rt, tid);
            pass_crx<100, 1000, 10, 1, false>(st, Vm, tid);
            // chain mode2: V^T(2), R(2->3), V(2)
            pass_crx<10, 1000, 100, 1, false>(st, Vt, tid);
            pass_crx<1, 10, 1000, 100, true >(st, Rt, tid);
            pass_crx<10, 1000, 100, 1, false>(st, Vm, tid);
        } else {
            pass_cx<1000, 100, 10, 1>(st, Ut, tid);    // (0,1)
            pass_cx<1000, 10, 100, 1>(st, Ut, tid);    // (0,2)
            pass_cx<1000, 1, 100, 10>(st, Ut, tid);    // (0,3)
            pass_cx<100, 10, 1000, 1>(st, Ut, tid);    // (1,2)
            pass_cx<100, 1, 1000, 10>(st, Ut, tid);    // (1,3)
            pass_cx<10, 1, 1000, 100>(st, Ut, tid);    // (2,3)
        }

        // ---- 4 BS gates (photon-number blocks) ----
        pass_bs<1000, 100, 10, 1>(st, BSb, tid);   // (0,1)
        pass_bs<100, 10, 1000, 1>(st, BSb, tid);   // (1,2)
        pass_bs<10, 1, 1000, 100>(st, BSb, tid);   // (2,3)
        pass_bs<1, 1000, 100, 10>(st, BSb, tid);   // (3,0)

        // ---- 4 merged single-mode E = D@S gates ----
        pass_e(st, Eg + (L * 4 + 0) * 100, 1000, tid);
        pass_e(st, Eg + (L * 4 + 1) * 100, 100,  tid);
        pass_e(st, Eg + (L * 4 + 2) * 100, 10,   tid);
        pass_e(st, Eg + (L * 4 + 3) * 100, 1,    tid);
    }

    // ---- photon-number readout on modes 0..2, dense head ----
    float p0 = 0.f, p1 = 0.f, p2 = 0.f;
    for (int e = tid; e < 10000; e += NTHR) {
        float2 v = st[e];
        float pr = v.x * v.x + v.y * v.y;
        int i0 = e / 1000; int r = e - i0 * 1000;
        int i1 = r / 100;  r -= i1 * 100;
        int i2 = r / 10;
        p0 += pr * (float)i0;
        p1 += pr * (float)i1;
        p2 += pr * (float)i2;
    }
#pragma unroll
    for (int o = 16; o > 0; o >>= 1) {
        p0 += __shfl_down_sync(0xffffffffu, p0, o);
        p1 += __shfl_down_sync(0xffffffffu, p1, o);
        p2 += __shfl_down_sync(0xffffffffu, p2, o);
    }
    int wid = tid >> 5, lane = tid & 31;
    if (lane == 0) { redsh[wid] = p0; redsh[32 + wid] = p1; redsh[64 + wid] = p2; }
    __syncthreads();
    if (tid == 0) {
        float q0 = 0.f, q1 = 0.f, q2 = 0.f;
        for (int w = 0; w < 32; w++) { q0 += redsh[w]; q1 += redsh[32 + w]; q2 += redsh[64 + w]; }
        out[b] = q0 * w_dense[0] + q1 * w_dense[1] + q2 * w_dense[2] + b_dense[0];
    }
}

// ---------------- launch -----------------------------------------------------
extern "C" void kernel_launch(void* const* d_in, const int* in_sizes, int n_in,
                              void* d_out, int out_size) {
    const float* jets    = (const float*)d_in[0];
    const float* s_scale = (const float*)d_in[1];
    const float* dmag    = (const float*)d_in[2];
    const float* dph     = (const float*)d_in[3];
    const float* smag    = (const float*)d_in[4];
    const float* sph     = (const float*)d_in[5];
    const float* w_dense = (const float*)d_in[6];
    const float* b_dense = (const float*)d_in[7];
    float* out = (float*)d_out;

    const int smem_main = SM_FLOATS * 4;   // 139760 bytes
    const int smem_g = 10000 * 8;          // 80000 bytes
    cudaFuncSetAttribute(k_main,     cudaFuncAttributeMaxDynamicSharedMemorySize, smem_main);
    cudaFuncSetAttribute(k_g_taylor, cudaFuncAttributeMaxDynamicSharedMemorySize, smem_g);
    cudaFuncSetAttribute(k_g_square, cudaFuncAttributeMaxDynamicSharedMemorySize, smem_g);

    k_enc<<<NB * 4 + 8, 128>>>(jets, s_scale, dmag, dph, smag, sph);
    k_eig<<<1, 32>>>();
    k_g_init<<<2, 512>>>();
    for (int j = 2; j <= 13; j++)
        k_g_taylor<<<40, 512, smem_g>>>(j, j & 1);
    for (int it = 0; it < 6; it++)
        k_g_square<<<40, 512, smem_g>>>(it & 1);
    k_conj1<<<20, 512>>>();
    k_conj2<<<20, 512>>>();
    k_checkpack<<<1, 512>>>();
    k_pack<<<55, 256>>>();
    k_main<<<NB, NTHR, smem_main>>>(w_dense, b_dense, out);
}